// round 1
// baseline (speedup 1.0000x reference)
#include <cuda_runtime.h>
#include <cuda_bf16.h>

// ---------------------------------------------------------------------------
// VQ-VAE forward:
//   h1 = relu(x @ enc0_w^T + enc0_b)        [8192,2048] -> [8192,1024]
//   h2 = relu(h1 @ enc1_w^T + enc1_b)       -> [8192,512]
//   z  = h2 @ z_w^T + z_b                   -> [8192,256]
//   z_q = VQ(z, codebook)  (view [32768,64], argmin dist, gather, STE)
//   d1 = relu(z_q @ dec0_w^T + dec0_b)      -> [8192,512]
//   d2 = relu(d1 @ dec1_w^T + dec1_b)       -> [8192,1024]
//   out = d2 @ out_w^T + out_b              -> [8192,2048]
// All fp32. Both GEMM operands are K-contiguous (A[M,K], W[N,K]).
// ---------------------------------------------------------------------------

#define M_ROWS 8192
#define EMB_NUM 1024
#define EMB_DIM 64

// Scratch (static device globals -- allocation-free rule)
__device__ float g_h1[8192 * 1024];
__device__ float g_h2[8192 * 512];
__device__ float g_z [8192 * 256];
__device__ float g_zq[8192 * 256];
__device__ float g_d1[8192 * 512];
__device__ float g_d2[8192 * 1024];
__device__ float g_cn[EMB_NUM];

// ---------------------------------------------------------------------------
// Tiled SGEMM: C[M,N] = A[M,K] @ W[N,K]^T + bias[N], optional ReLU.
// Requires: M % BM == 0, N % BN == 0, K % BK == 0 (true for all shapes here).
// ---------------------------------------------------------------------------
template <int BM, int BN, int BK, int TM, int TN, bool RELU>
__global__ __launch_bounds__((BM / TM) * (BN / TN))
void gemm_bias_kernel(const float* __restrict__ A,
                      const float* __restrict__ W,
                      const float* __restrict__ bias,
                      float* __restrict__ C,
                      int M, int N, int K) {
    constexpr int THREADS = (BM / TM) * (BN / TN);
    constexpr int PAD = 4;
    __shared__ float As[BK][BM + PAD];
    __shared__ float Ws[BK][BN + PAD];

    const int bm = blockIdx.y * BM;
    const int bn = blockIdx.x * BN;
    const int tid = threadIdx.x;
    const int tx = tid % (BN / TN);   // 0..15
    const int ty = tid / (BN / TN);   // 0..15

    float acc[TM][TN];
#pragma unroll
    for (int i = 0; i < TM; i++)
#pragma unroll
        for (int j = 0; j < TN; j++) acc[i][j] = 0.0f;

    for (int k0 = 0; k0 < K; k0 += BK) {
        // Load A tile (BM x BK) transposed into As[BK][BM]
#pragma unroll
        for (int i = tid; i < BM * BK / 4; i += THREADS) {
            int r  = i / (BK / 4);
            int c4 = i % (BK / 4);
            float4 v = *reinterpret_cast<const float4*>(A + (size_t)(bm + r) * K + k0 + c4 * 4);
            As[c4 * 4 + 0][r] = v.x;
            As[c4 * 4 + 1][r] = v.y;
            As[c4 * 4 + 2][r] = v.z;
            As[c4 * 4 + 3][r] = v.w;
        }
        // Load W tile (BN x BK) transposed into Ws[BK][BN]
#pragma unroll
        for (int i = tid; i < BN * BK / 4; i += THREADS) {
            int r  = i / (BK / 4);
            int c4 = i % (BK / 4);
            float4 v = *reinterpret_cast<const float4*>(W + (size_t)(bn + r) * K + k0 + c4 * 4);
            Ws[c4 * 4 + 0][r] = v.x;
            Ws[c4 * 4 + 1][r] = v.y;
            Ws[c4 * 4 + 2][r] = v.z;
            Ws[c4 * 4 + 3][r] = v.w;
        }
        __syncthreads();

#pragma unroll
        for (int k = 0; k < BK; k++) {
            float a[TM], b[TN];
            // 16B-aligned fragment reads (row starts are 16B aligned: (BM+4)*4*k is mult of 16)
            *reinterpret_cast<float4*>(&a[0]) = *reinterpret_cast<const float4*>(&As[k][ty * TM + 0]);
            *reinterpret_cast<float4*>(&a[4]) = *reinterpret_cast<const float4*>(&As[k][ty * TM + 4]);
            *reinterpret_cast<float4*>(&b[0]) = *reinterpret_cast<const float4*>(&Ws[k][tx * TN + 0]);
            *reinterpret_cast<float4*>(&b[4]) = *reinterpret_cast<const float4*>(&Ws[k][tx * TN + 4]);
#pragma unroll
            for (int i = 0; i < TM; i++)
#pragma unroll
                for (int j = 0; j < TN; j++)
                    acc[i][j] = fmaf(a[i], b[j], acc[i][j]);
        }
        __syncthreads();
    }

    // Epilogue: bias (+ ReLU), vectorized stores
    float bv[TN];
#pragma unroll
    for (int j = 0; j < TN; j++) bv[j] = bias[bn + tx * TN + j];

#pragma unroll
    for (int i = 0; i < TM; i++) {
        int row = bm + ty * TM + i;
        float out[TN];
#pragma unroll
        for (int j = 0; j < TN; j++) {
            float v = acc[i][j] + bv[j];
            if (RELU) v = fmaxf(v, 0.0f);
            out[j] = v;
        }
        float* cptr = C + (size_t)row * N + bn + tx * TN;
        *reinterpret_cast<float4*>(cptr + 0) = *reinterpret_cast<float4*>(&out[0]);
        *reinterpret_cast<float4*>(cptr + 4) = *reinterpret_cast<float4*>(&out[4]);
    }
}

// ---------------------------------------------------------------------------
// Codebook squared norms: cn[i] = sum_d codebook[i][d]^2
// ---------------------------------------------------------------------------
__global__ void cnorm_kernel(const float* __restrict__ cb, float* __restrict__ cn) {
    int i = blockIdx.x * blockDim.x + threadIdx.x;
    if (i >= EMB_NUM) return;
    const float4* p = reinterpret_cast<const float4*>(cb + (size_t)i * EMB_DIM);
    float s = 0.0f;
#pragma unroll
    for (int d = 0; d < EMB_DIM / 4; d++) {
        float4 v = p[d];
        s += v.x * v.x + v.y * v.y + v.z * v.z + v.w * v.w;
    }
    cn[i] = s;
}

// ---------------------------------------------------------------------------
// Vector quantization: one thread per 64-dim row (32768 rows).
// dist(j) = ||c_j||^2 + (-2 z) . c_j   (row-constant ||z||^2 dropped; argmin
// unchanged). First minimum kept (strict <) to match jnp.argmin.
// STE replayed as z + (z_q - z) to match reference fp32 rounding.
// Codebook streamed through smem in 128-code (32KB) chunks; all threads read
// the same code element in lockstep -> LDS broadcast.
// ---------------------------------------------------------------------------
__global__ __launch_bounds__(256)
void vq_kernel(const float* __restrict__ z,
               const float* __restrict__ cb,
               const float* __restrict__ cn,
               float* __restrict__ zq) {
    constexpr int CHUNK = 128;
    __shared__ float sc[CHUNK][EMB_DIM];
    __shared__ float scn[CHUNK];

    const int row = blockIdx.x * blockDim.x + threadIdx.x;  // 0..32767
    const float* zp = z + (size_t)row * EMB_DIM;

    float m2z[EMB_DIM];  // -2 * z_row
#pragma unroll
    for (int d = 0; d < EMB_DIM / 4; d++) {
        float4 v = reinterpret_cast<const float4*>(zp)[d];
        m2z[d * 4 + 0] = -2.0f * v.x;
        m2z[d * 4 + 1] = -2.0f * v.y;
        m2z[d * 4 + 2] = -2.0f * v.z;
        m2z[d * 4 + 3] = -2.0f * v.w;
    }

    float best = 3.0e38f;
    int bidx = 0;

    for (int ch = 0; ch < EMB_NUM / CHUNK; ch++) {
        __syncthreads();
        // load chunk: 128*64 floats = 2048 float4, 256 threads -> 8 each
        const float4* src = reinterpret_cast<const float4*>(cb + (size_t)ch * CHUNK * EMB_DIM);
        float4* dst = reinterpret_cast<float4*>(&sc[0][0]);
#pragma unroll
        for (int i = threadIdx.x; i < CHUNK * EMB_DIM / 4; i += 256) dst[i] = src[i];
        if (threadIdx.x < CHUNK) scn[threadIdx.x] = cn[ch * CHUNK + threadIdx.x];
        __syncthreads();

        for (int j = 0; j < CHUNK; j++) {
            float s = scn[j];
#pragma unroll
            for (int d = 0; d < EMB_DIM; d++) s = fmaf(sc[j][d], m2z[d], s);
            int gidx = ch * CHUNK + j;
            if (s < best) { best = s; bidx = gidx; }
        }
    }

    // gather + straight-through: out = z + (c - z)
    const float4* cp = reinterpret_cast<const float4*>(cb + (size_t)bidx * EMB_DIM);
    const float4* zp4 = reinterpret_cast<const float4*>(zp);
    float4* op = reinterpret_cast<float4*>(zq + (size_t)row * EMB_DIM);
#pragma unroll
    for (int d = 0; d < EMB_DIM / 4; d++) {
        float4 c = cp[d], zz = zp4[d], o;
        o.x = zz.x + (c.x - zz.x);
        o.y = zz.y + (c.y - zz.y);
        o.z = zz.z + (c.z - zz.z);
        o.w = zz.w + (c.w - zz.w);
        op[d] = o;
    }
}

// ---------------------------------------------------------------------------
// Launch
// ---------------------------------------------------------------------------
static inline void launch_gemm(const float* A, const float* W, const float* b,
                               float* C, int M, int N, int K, bool relu,
                               cudaStream_t s) {
    dim3 grid(N / 128, M / 128);
    if (relu)
        gemm_bias_kernel<128, 128, 16, 8, 8, true ><<<grid, 256, 0, s>>>(A, W, b, C, M, N, K);
    else
        gemm_bias_kernel<128, 128, 16, 8, 8, false><<<grid, 256, 0, s>>>(A, W, b, C, M, N, K);
}

extern "C" void kernel_launch(void* const* d_in, const int* in_sizes, int n_in,
                              void* d_out, int out_size) {
    const float* x        = (const float*)d_in[0];
    const float* enc0_w   = (const float*)d_in[1];
    const float* enc0_b   = (const float*)d_in[2];
    const float* enc1_w   = (const float*)d_in[3];
    const float* enc1_b   = (const float*)d_in[4];
    const float* z_w      = (const float*)d_in[5];
    const float* z_b      = (const float*)d_in[6];
    const float* codebook = (const float*)d_in[7];
    const float* dec0_w   = (const float*)d_in[8];
    const float* dec0_b   = (const float*)d_in[9];
    const float* dec1_w   = (const float*)d_in[10];
    const float* dec1_b   = (const float*)d_in[11];
    const float* out_w    = (const float*)d_in[12];
    const float* out_b    = (const float*)d_in[13];
    float* out = (float*)d_out;

    float *h1, *h2, *z, *zq, *d1, *d2, *cn;
    cudaGetSymbolAddress((void**)&h1, g_h1);
    cudaGetSymbolAddress((void**)&h2, g_h2);
    cudaGetSymbolAddress((void**)&z,  g_z);
    cudaGetSymbolAddress((void**)&zq, g_zq);
    cudaGetSymbolAddress((void**)&d1, g_d1);
    cudaGetSymbolAddress((void**)&d2, g_d2);
    cudaGetSymbolAddress((void**)&cn, g_cn);

    cudaStream_t s = 0;

    // encoder
    launch_gemm(x,  enc0_w, enc0_b, h1, M_ROWS, 1024, 2048, true,  s);
    launch_gemm(h1, enc1_w, enc1_b, h2, M_ROWS, 512,  1024, true,  s);
    launch_gemm(h2, z_w,    z_b,    z,  M_ROWS, 256,  512,  false, s);

    // vector quantization
    cnorm_kernel<<<4, 256, 0, s>>>(codebook, cn);
    vq_kernel<<<(M_ROWS * 256 / EMB_DIM) / 256, 256, 0, s>>>(z, codebook, cn, zq);

    // decoder
    launch_gemm(zq, dec0_w, dec0_b, d1, M_ROWS, 512,  256,  true,  s);
    launch_gemm(d1, dec1_w, dec1_b, d2, M_ROWS, 1024, 512,  true,  s);
    launch_gemm(d2, out_w,  out_b,  out, M_ROWS, 2048, 1024, false, s);
}